// round 15
// baseline (speedup 1.0000x reference)
#include <cuda_runtime.h>
#include <cuda_fp16.h>
#include <math.h>
#include <stdint.h>

#define BATCH 32
#define CIN   256
#define COUT  256
#define NEXP  4
#define HH    56
#define WW    56
#define HWSZ  3136

#define PADW    58
#define QCNT    3364           // 58*58 padded positions
#define GUARD   64
#define ROWSPAD 3712           // GUARD + 28*128 + GUARD
#define MTILES  27             // ceil(3364/128)

// ---------------------------------------------------------------------------
// Scratch (__device__ globals zero-initialized; guard/border rows stay 0)
// ---------------------------------------------------------------------------
__device__ float g_pooled[BATCH * CIN];   // RAW spatial sums (scaled in att)
__device__ float g_att[BATCH * NEXP];
__device__ __half g_xt[(size_t)BATCH * ROWSPAD * CIN];
__device__ __half g_wf[(size_t)BATCH * 9 * COUT * CIN];

// ---------------------------------------------------------------------------
// PTX helpers (compute_80-era: valid on compute_103 base target)
// ---------------------------------------------------------------------------
__device__ __forceinline__ uint32_t smem_u32(const void* p) {
    uint32_t a;
    asm("{ .reg .u64 t; cvta.to.shared.u64 t, %1; cvt.u32.u64 %0, t; }"
        : "=r"(a) : "l"(p));
    return a;
}
#define CP_ASYNC16(dst, src) \
    asm volatile("cp.async.cg.shared.global [%0], [%1], 16;" \
                 :: "r"(dst), "l"(src) : "memory")
#define CP_COMMIT() asm volatile("cp.async.commit_group;" ::: "memory")
#define CP_WAIT1()  asm volatile("cp.async.wait_group 1;" ::: "memory")

#define LDSM4(r, addr) \
    asm volatile("ldmatrix.sync.aligned.m8n8.x4.shared.b16 {%0,%1,%2,%3}, [%4];" \
                 : "=r"((r)[0]), "=r"((r)[1]), "=r"((r)[2]), "=r"((r)[3]) \
                 : "r"(addr))

#define MMA16816(d, a, b0, b1) \
    asm volatile("mma.sync.aligned.m16n8k16.row.col.f32.f16.f16.f32 " \
                 "{%0,%1,%2,%3}, {%4,%5,%6,%7}, {%8,%9}, {%0,%1,%2,%3};" \
                 : "+f"((d)[0]), "+f"((d)[1]), "+f"((d)[2]), "+f"((d)[3]) \
                 : "r"((a)[0]), "r"((a)[1]), "r"((a)[2]), "r"((a)[3]), \
                   "r"(b0), "r"(b1))

// ---------------------------------------------------------------------------
// Kernel 0: zero g_pooled (graph replays re-accumulate atomically)
// ---------------------------------------------------------------------------
__global__ void zero_kernel() {
    int i = blockIdx.x * 256 + threadIdx.x;
    if (i < BATCH * CIN) g_pooled[i] = 0.f;
}

// ---------------------------------------------------------------------------
// Kernel 1: transpose x -> padded position-major fp16, FUSED spatial-sum
// (atomicAdd of per-block partial sums into g_pooled raw sums).
// ---------------------------------------------------------------------------
__global__ void __launch_bounds__(256) transpose_kernel(const float* __restrict__ x) {
    __shared__ float tile[64][33];
    int b   = blockIdx.z;
    int ci0 = blockIdx.y * 64;
    int p0  = blockIdx.x * 32;
    int tid = threadIdx.x;
    int px = tid & 31, cir = tid >> 5;
    #pragma unroll
    for (int i = 0; i < 8; i++) {
        int ci = cir * 8 + i;
        tile[ci][px] = x[((size_t)b * CIN + ci0 + ci) * HWSZ + p0 + px];
    }
    __syncthreads();
    // fused mean partial: threads 0..63 sum their ci row over the 32 pixels
    if (tid < 64) {
        float s = 0.f;
        #pragma unroll
        for (int j = 0; j < 32; j++) s += tile[tid][j];
        atomicAdd(&g_pooled[b * CIN + ci0 + tid], s);
    }
    int cc = tid & 7, r = tid >> 3;
    int p = p0 + r;
    int h = p / WW, w = p % WW;
    size_t row = (size_t)b * ROWSPAD + GUARD + (size_t)(h + 1) * PADW + (w + 1);
    __align__(16) __half h8[8];
    #pragma unroll
    for (int j = 0; j < 8; j++)
        h8[j] = __float2half_rn(tile[cc * 8 + j][r]);
    *reinterpret_cast<uint4*>(g_xt + row * CIN + ci0 + cc * 8) =
        *reinterpret_cast<const uint4*>(h8);
}

// ---------------------------------------------------------------------------
// Kernel 2: att = sigmoid((pooled_raw/HWSZ) @ att_w^T). 1 block, 128 threads.
// ---------------------------------------------------------------------------
__global__ void att_kernel(const float* __restrict__ att_w) {
    int idx = threadIdx.x;
    int b = idx >> 2, k = idx & 3;
    const float* pr = g_pooled + b * CIN;
    const float* wr = att_w + k * CIN;
    float s = 0.f;
    #pragma unroll 8
    for (int c = 0; c < CIN; c++) s += pr[c] * wr[c];
    s *= (1.0f / (float)HWSZ);
    g_att[idx] = 1.0f / (1.0f + expf(-s));
}

// ---------------------------------------------------------------------------
// Kernel 3: wprep (no att recompute — reads g_att). One block per cout:
// stage 4-expert slice (36KB) once, sweep 32 batches, coalesced fp16 stores.
// ---------------------------------------------------------------------------
__global__ void __launch_bounds__(256) wprep_kernel(const float* __restrict__ weight) {
    __shared__ float ws[NEXP][CIN * 9];
    __shared__ float att_s[BATCH * NEXP];
    const int o = blockIdx.x, ci = threadIdx.x;
    if (threadIdx.x < BATCH * NEXP) att_s[threadIdx.x] = g_att[threadIdx.x];
    #pragma unroll
    for (int k = 0; k < NEXP; k++)
        for (int i = threadIdx.x; i < CIN * 9; i += 256)
            ws[k][i] = weight[((size_t)k * COUT + o) * (CIN * 9) + i];
    __syncthreads();
    for (int b = 0; b < BATCH; b++) {
        float a0 = att_s[b * NEXP + 0], a1 = att_s[b * NEXP + 1];
        float a2 = att_s[b * NEXP + 2], a3 = att_s[b * NEXP + 3];
        #pragma unroll
        for (int t = 0; t < 9; t++) {
            float v = a0 * ws[0][ci * 9 + t] + a1 * ws[1][ci * 9 + t]
                    + a2 * ws[2][ci * 9 + t] + a3 * ws[3][ci * 9 + t];
            g_wf[(((size_t)b * 9 + t) * COUT + o) * CIN + ci] = __float2half_rn(v);
        }
    }
}

// ---------------------------------------------------------------------------
// Kernel 4: implicit-GEMM conv — UNCHANGED from R14 best (348.9us).
// CTA tile M=128 x N=128, 8 warps (4M x 2N, warp 32x64), k16 ping-pong,
// A double-buffered halos, B 3-deep ring, one commit/stage, wait_group 1.
// SMEM: 2x32K + 3x16K = 112KB -> 2 CTAs/SM. Regs capped 128.
// ---------------------------------------------------------------------------
#define A_BYTES   32768
#define B_STG     16384
#define SMEM_BYTES_MMA (2 * A_BYTES + 3 * B_STG)
#define SWZ_RC(r, c) ((uint32_t)((r) * 128 + (((c) ^ ((r) & 7)) << 4)))

__global__ void __launch_bounds__(256, 2) conv_mma(float* __restrict__ out) {
    extern __shared__ char smem[];
    const uint32_t sbase = smem_u32(smem);
    const int tid = threadIdx.x, wid = tid >> 5, lid = tid & 31;
    const int b  = blockIdx.y;
    const int mt = blockIdx.x >> 1, nt = blockIdx.x & 1;
    const int q0 = mt * 128, n0 = nt * 128;
    const int mwarp = wid >> 1, nwarp = wid & 1;

    const __half* xsrc = g_xt + (size_t)b * ROWSPAD * CIN;
    const __half* wsrc = g_wf + (size_t)b * 9 * COUT * CIN;

    float acc[2][8][4];
    #pragma unroll
    for (int mi = 0; mi < 2; mi++)
        #pragma unroll
        for (int ni = 0; ni < 8; ni++)
            #pragma unroll
            for (int e = 0; e < 4; e++) acc[mi][ni][e] = 0.f;

    auto issueA = [&](int c4) {
        const int ci0 = c4 << 6;
        const uint32_t abuf = sbase + (uint32_t)(c4 & 1) * A_BYTES;
        #pragma unroll
        for (int i = 0; i < 8; i++) {
            int j = tid + i * 256;
            int r = j >> 3, c = j & 7;
            const __half* src = xsrc + (size_t)(q0 + r) * CIN + ci0 + c * 8;
            CP_ASYNC16(abuf + SWZ_RC(r, c), src);
        }
    };
    auto issueB = [&](int s) {
        const int c4 = s / 9, t = s - c4 * 9;
        const int ci0 = c4 << 6;
        const uint32_t stg = sbase + 2 * A_BYTES + (uint32_t)(s % 3) * B_STG;
        #pragma unroll
        for (int i = 0; i < 4; i++) {
            int j = tid + i * 256;
            int r = j >> 3, c = j & 7;
            const __half* src =
                wsrc + ((size_t)t * COUT + n0 + r) * CIN + ci0 + c * 8;
            CP_ASYNC16(stg + SWZ_RC(r, c), src);
        }
    };

    // Prologue: G0 = {A(0), B(0)}, G1 = {B(1)}
    issueA(0); issueB(0); CP_COMMIT();
    issueB(1); CP_COMMIT();

    const int lr = lid & 15, lc = lid >> 4;

    for (int s = 0; s < 36; s++) {
        const int c4 = s / 9, t = s - c4 * 9;
        CP_WAIT1();
        __syncthreads();
        if (t == 6 && c4 < 3) issueA(c4 + 1);
        if (s + 2 < 36) issueB(s + 2);
        CP_COMMIT();

        const int off = (t / 3 - 1) * PADW + (t % 3 - 1);
        const int arow0 = 64 + off + mwarp * 32;
        const uint32_t Abuf = sbase + (uint32_t)(c4 & 1) * A_BYTES;
        const uint32_t Bbuf = sbase + 2 * A_BYTES + (uint32_t)(s % 3) * B_STG;

        uint32_t af[2][2][4], bf[2][4][4];
        #pragma unroll
        for (int mi = 0; mi < 2; mi++) {
            int row = arow0 + mi * 16 + lr;
            LDSM4(af[0][mi], Abuf + row * 128 +
                  ((uint32_t)(lc ^ (row & 7)) << 4));
        }
        #pragma unroll
        for (int nj = 0; nj < 4; nj++) {
            int row = nwarp * 64 + nj * 16 + lr;
            LDSM4(bf[0][nj], Bbuf + row * 128 +
                  ((uint32_t)(lc ^ (row & 7)) << 4));
        }
        #pragma unroll
        for (int k16 = 0; k16 < 4; k16++) {
            const int cur = k16 & 1, nxt = cur ^ 1;
            if (k16 < 3) {
                #pragma unroll
                for (int mi = 0; mi < 2; mi++) {
                    int row = arow0 + mi * 16 + lr;
                    LDSM4(af[nxt][mi], Abuf + row * 128 +
                          ((uint32_t)(((k16 + 1) * 2 + lc) ^ (row & 7)) << 4));
                }
                #pragma unroll
                for (int nj = 0; nj < 4; nj++) {
                    int row = nwarp * 64 + nj * 16 + lr;
                    LDSM4(bf[nxt][nj], Bbuf + row * 128 +
                          ((uint32_t)(((k16 + 1) * 2 + lc) ^ (row & 7)) << 4));
                }
            }
            #pragma unroll
            for (int mi = 0; mi < 2; mi++)
                #pragma unroll
                for (int nj = 0; nj < 4; nj++) {
                    MMA16816(acc[mi][2 * nj + 0], af[cur][mi],
                             bf[cur][nj][0], bf[cur][nj][2]);
                    MMA16816(acc[mi][2 * nj + 1], af[cur][mi],
                             bf[cur][nj][1], bf[cur][nj][3]);
                }
        }
    }

    // ---- epilogue: scatter acc to out[b][cout][h*56+w] ----
    const int gr = lid >> 2, c2 = (lid & 3) * 2;
    float* outb = out + (size_t)b * COUT * HWSZ;
    #pragma unroll
    for (int mi = 0; mi < 2; mi++) {
        int qa = q0 + mwarp * 32 + mi * 16 + gr;
        int qb = qa + 8;
        int ha = qa / PADW - 1, wa = qa % PADW - 1;
        int hb = qb / PADW - 1, wb = qb % PADW - 1;
        bool va = ((unsigned)ha < HH) && ((unsigned)wa < WW);
        bool vb = ((unsigned)hb < HH) && ((unsigned)wb < WW);
        int pa = ha * WW + wa, pb = hb * WW + wb;
        #pragma unroll
        for (int ni = 0; ni < 8; ni++) {
            int n = n0 + nwarp * 64 + ni * 8 + c2;
            float* p = outb + (size_t)n * HWSZ;
            if (va) { p[pa] = acc[mi][ni][0]; p[HWSZ + pa] = acc[mi][ni][1]; }
            if (vb) { p[pb] = acc[mi][ni][2]; p[HWSZ + pb] = acc[mi][ni][3]; }
        }
    }
}

// ---------------------------------------------------------------------------
extern "C" void kernel_launch(void* const* d_in, const int* in_sizes, int n_in,
                              void* d_out, int out_size) {
    const float* x      = (const float*)d_in[0];  // (32,256,56,56)
    const float* att_w  = (const float*)d_in[1];  // (4,256)
    const float* weight = (const float*)d_in[2];  // (4,256,256,3,3)
    float* out = (float*)d_out;                   // (32,256,56,56)

    cudaFuncSetAttribute(conv_mma, cudaFuncAttributeMaxDynamicSharedMemorySize,
                         SMEM_BYTES_MMA);

    zero_kernel<<<(BATCH * CIN + 255) / 256, 256>>>();
    transpose_kernel<<<dim3(98, 4, BATCH), 256>>>(x);   // + fused mean sums
    att_kernel<<<1, 128>>>(att_w);
    wprep_kernel<<<COUT, 256>>>(weight);
    conv_mma<<<dim3(MTILES * 2, BATCH), 256, SMEM_BYTES_MMA>>>(out);
}

// round 16
// speedup vs baseline: 1.4147x; 1.4147x over previous
#include <cuda_runtime.h>
#include <cuda_fp16.h>
#include <math.h>
#include <stdint.h>

#define BATCH 32
#define CIN   256
#define COUT  256
#define NEXP  4
#define HH    56
#define WW    56
#define HWSZ  3136

#define PADW    58
#define QCNT    3364           // 58*58 padded positions
#define GUARD   64
#define ROWSPAD 3712           // GUARD + 28*128 + GUARD
#define MTILES  27             // ceil(3364/128)

// ---------------------------------------------------------------------------
// Scratch (__device__ globals zero-initialized; guard/border rows stay 0)
// ---------------------------------------------------------------------------
__device__ float g_pooled[BATCH * CIN];   // per-(b,c) spatial mean
__device__ float g_att[BATCH * NEXP];
__device__ __half g_xt[(size_t)BATCH * ROWSPAD * CIN];
__device__ __half g_wf[(size_t)BATCH * 9 * COUT * CIN];

// ---------------------------------------------------------------------------
// PTX helpers (compute_80-era: valid on compute_103 base target)
// ---------------------------------------------------------------------------
__device__ __forceinline__ uint32_t smem_u32(const void* p) {
    uint32_t a;
    asm("{ .reg .u64 t; cvta.to.shared.u64 t, %1; cvt.u32.u64 %0, t; }"
        : "=r"(a) : "l"(p));
    return a;
}
#define CP_ASYNC16(dst, src) \
    asm volatile("cp.async.cg.shared.global [%0], [%1], 16;" \
                 :: "r"(dst), "l"(src) : "memory")
#define CP_COMMIT() asm volatile("cp.async.commit_group;" ::: "memory")
#define CP_WAIT1()  asm volatile("cp.async.wait_group 1;" ::: "memory")

#define LDSM4(r, addr) \
    asm volatile("ldmatrix.sync.aligned.m8n8.x4.shared.b16 {%0,%1,%2,%3}, [%4];" \
                 : "=r"((r)[0]), "=r"((r)[1]), "=r"((r)[2]), "=r"((r)[3]) \
                 : "r"(addr))

#define MMA16816(d, a, b0, b1) \
    asm volatile("mma.sync.aligned.m16n8k16.row.col.f32.f16.f16.f32 " \
                 "{%0,%1,%2,%3}, {%4,%5,%6,%7}, {%8,%9}, {%0,%1,%2,%3};" \
                 : "+f"((d)[0]), "+f"((d)[1]), "+f"((d)[2]), "+f"((d)[3]) \
                 : "r"((a)[0]), "r"((a)[1]), "r"((a)[2]), "r"((a)[3]), \
                   "r"(b0), "r"(b1))

// ---------------------------------------------------------------------------
// Kernel 1: per-(b,c) spatial mean (R14-proven)
// ---------------------------------------------------------------------------
__global__ void mean_kernel(const float* __restrict__ x) {
    int bc = blockIdx.x;
    const float4* p = reinterpret_cast<const float4*>(x + (size_t)bc * HWSZ);
    float s = 0.f;
    for (int i = threadIdx.x; i < HWSZ / 4; i += 256) {
        float4 v = p[i];
        s += (v.x + v.y) + (v.z + v.w);
    }
    #pragma unroll
    for (int o = 16; o; o >>= 1) s += __shfl_xor_sync(0xffffffffu, s, o);
    __shared__ float ws[8];
    if ((threadIdx.x & 31) == 0) ws[threadIdx.x >> 5] = s;
    __syncthreads();
    if (threadIdx.x == 0) {
        float t = 0.f;
        #pragma unroll
        for (int i = 0; i < 8; i++) t += ws[i];
        g_pooled[bc] = t * (1.0f / (float)HWSZ);
    }
}

// ---------------------------------------------------------------------------
// Kernel 2: transpose x -> padded position-major fp16 (R14-proven, no atomics)
// ---------------------------------------------------------------------------
__global__ void __launch_bounds__(256) transpose_kernel(const float* __restrict__ x) {
    __shared__ float tile[64][33];
    int b   = blockIdx.z;
    int ci0 = blockIdx.y * 64;
    int p0  = blockIdx.x * 32;
    int tid = threadIdx.x;
    int px = tid & 31, cir = tid >> 5;
    #pragma unroll
    for (int i = 0; i < 8; i++) {
        int ci = cir * 8 + i;
        tile[ci][px] = x[((size_t)b * CIN + ci0 + ci) * HWSZ + p0 + px];
    }
    __syncthreads();
    int cc = tid & 7, r = tid >> 3;
    int p = p0 + r;
    int h = p / WW, w = p % WW;
    size_t row = (size_t)b * ROWSPAD + GUARD + (size_t)(h + 1) * PADW + (w + 1);
    __align__(16) __half h8[8];
    #pragma unroll
    for (int j = 0; j < 8; j++)
        h8[j] = __float2half_rn(tile[cc * 8 + j][r]);
    *reinterpret_cast<uint4*>(g_xt + row * CIN + ci0 + cc * 8) =
        *reinterpret_cast<const uint4*>(h8);
}

// ---------------------------------------------------------------------------
// Kernel 3: att = sigmoid(pooled @ att_w^T). 1 block, 128 threads.
// ---------------------------------------------------------------------------
__global__ void att_kernel(const float* __restrict__ att_w) {
    int idx = threadIdx.x;
    int b = idx >> 2, k = idx & 3;
    const float* pr = g_pooled + b * CIN;
    const float* wr = att_w + k * CIN;
    float s = 0.f;
    #pragma unroll 8
    for (int c = 0; c < CIN; c++) s += pr[c] * wr[c];
    g_att[idx] = 1.0f / (1.0f + expf(-s));
}

// ---------------------------------------------------------------------------
// Kernel 4: lean wprep (R15-measured 23us): reads g_att, one block per cout,
// stage 4-expert slice (36KB) once, sweep 32 batches, coalesced fp16 stores.
// ---------------------------------------------------------------------------
__global__ void __launch_bounds__(256) wprep_kernel(const float* __restrict__ weight) {
    __shared__ float ws[NEXP][CIN * 9];
    __shared__ float att_s[BATCH * NEXP];
    const int o = blockIdx.x, ci = threadIdx.x;
    if (threadIdx.x < BATCH * NEXP) att_s[threadIdx.x] = g_att[threadIdx.x];
    #pragma unroll
    for (int k = 0; k < NEXP; k++)
        for (int i = threadIdx.x; i < CIN * 9; i += 256)
            ws[k][i] = weight[((size_t)k * COUT + o) * (CIN * 9) + i];
    __syncthreads();
    for (int b = 0; b < BATCH; b++) {
        float a0 = att_s[b * NEXP + 0], a1 = att_s[b * NEXP + 1];
        float a2 = att_s[b * NEXP + 2], a3 = att_s[b * NEXP + 3];
        #pragma unroll
        for (int t = 0; t < 9; t++) {
            float v = a0 * ws[0][ci * 9 + t] + a1 * ws[1][ci * 9 + t]
                    + a2 * ws[2][ci * 9 + t] + a3 * ws[3][ci * 9 + t];
            g_wf[(((size_t)b * 9 + t) * COUT + o) * CIN + ci] = __float2half_rn(v);
        }
    }
}

// ---------------------------------------------------------------------------
// Kernel 5: implicit-GEMM conv — UNCHANGED R14 version (348.9us, frozen).
// ---------------------------------------------------------------------------
#define A_BYTES   32768
#define B_STG     16384
#define SMEM_BYTES_MMA (2 * A_BYTES + 3 * B_STG)
#define SWZ_RC(r, c) ((uint32_t)((r) * 128 + (((c) ^ ((r) & 7)) << 4)))

__global__ void __launch_bounds__(256, 2) conv_mma(float* __restrict__ out) {
    extern __shared__ char smem[];
    const uint32_t sbase = smem_u32(smem);
    const int tid = threadIdx.x, wid = tid >> 5, lid = tid & 31;
    const int b  = blockIdx.y;
    const int mt = blockIdx.x >> 1, nt = blockIdx.x & 1;
    const int q0 = mt * 128, n0 = nt * 128;
    const int mwarp = wid >> 1, nwarp = wid & 1;

    const __half* xsrc = g_xt + (size_t)b * ROWSPAD * CIN;
    const __half* wsrc = g_wf + (size_t)b * 9 * COUT * CIN;

    float acc[2][8][4];
    #pragma unroll
    for (int mi = 0; mi < 2; mi++)
        #pragma unroll
        for (int ni = 0; ni < 8; ni++)
            #pragma unroll
            for (int e = 0; e < 4; e++) acc[mi][ni][e] = 0.f;

    auto issueA = [&](int c4) {
        const int ci0 = c4 << 6;
        const uint32_t abuf = sbase + (uint32_t)(c4 & 1) * A_BYTES;
        #pragma unroll
        for (int i = 0; i < 8; i++) {
            int j = tid + i * 256;
            int r = j >> 3, c = j & 7;
            const __half* src = xsrc + (size_t)(q0 + r) * CIN + ci0 + c * 8;
            CP_ASYNC16(abuf + SWZ_RC(r, c), src);
        }
    };
    auto issueB = [&](int s) {
        const int c4 = s / 9, t = s - c4 * 9;
        const int ci0 = c4 << 6;
        const uint32_t stg = sbase + 2 * A_BYTES + (uint32_t)(s % 3) * B_STG;
        #pragma unroll
        for (int i = 0; i < 4; i++) {
            int j = tid + i * 256;
            int r = j >> 3, c = j & 7;
            const __half* src =
                wsrc + ((size_t)t * COUT + n0 + r) * CIN + ci0 + c * 8;
            CP_ASYNC16(stg + SWZ_RC(r, c), src);
        }
    };

    // Prologue: G0 = {A(0), B(0)}, G1 = {B(1)}
    issueA(0); issueB(0); CP_COMMIT();
    issueB(1); CP_COMMIT();

    const int lr = lid & 15, lc = lid >> 4;

    for (int s = 0; s < 36; s++) {
        const int c4 = s / 9, t = s - c4 * 9;
        CP_WAIT1();
        __syncthreads();
        if (t == 6 && c4 < 3) issueA(c4 + 1);
        if (s + 2 < 36) issueB(s + 2);
        CP_COMMIT();

        const int off = (t / 3 - 1) * PADW + (t % 3 - 1);
        const int arow0 = 64 + off + mwarp * 32;
        const uint32_t Abuf = sbase + (uint32_t)(c4 & 1) * A_BYTES;
        const uint32_t Bbuf = sbase + 2 * A_BYTES + (uint32_t)(s % 3) * B_STG;

        uint32_t af[2][2][4], bf[2][4][4];
        #pragma unroll
        for (int mi = 0; mi < 2; mi++) {
            int row = arow0 + mi * 16 + lr;
            LDSM4(af[0][mi], Abuf + row * 128 +
                  ((uint32_t)(lc ^ (row & 7)) << 4));
        }
        #pragma unroll
        for (int nj = 0; nj < 4; nj++) {
            int row = nwarp * 64 + nj * 16 + lr;
            LDSM4(bf[0][nj], Bbuf + row * 128 +
                  ((uint32_t)(lc ^ (row & 7)) << 4));
        }
        #pragma unroll
        for (int k16 = 0; k16 < 4; k16++) {
            const int cur = k16 & 1, nxt = cur ^ 1;
            if (k16 < 3) {
                #pragma unroll
                for (int mi = 0; mi < 2; mi++) {
                    int row = arow0 + mi * 16 + lr;
                    LDSM4(af[nxt][mi], Abuf + row * 128 +
                          ((uint32_t)(((k16 + 1) * 2 + lc) ^ (row & 7)) << 4));
                }
                #pragma unroll
                for (int nj = 0; nj < 4; nj++) {
                    int row = nwarp * 64 + nj * 16 + lr;
                    LDSM4(bf[nxt][nj], Bbuf + row * 128 +
                          ((uint32_t)(((k16 + 1) * 2 + lc) ^ (row & 7)) << 4));
                }
            }
            #pragma unroll
            for (int mi = 0; mi < 2; mi++)
                #pragma unroll
                for (int nj = 0; nj < 4; nj++) {
                    MMA16816(acc[mi][2 * nj + 0], af[cur][mi],
                             bf[cur][nj][0], bf[cur][nj][2]);
                    MMA16816(acc[mi][2 * nj + 1], af[cur][mi],
                             bf[cur][nj][1], bf[cur][nj][3]);
                }
        }
    }

    // ---- epilogue: scatter acc to out[b][cout][h*56+w] ----
    const int gr = lid >> 2, c2 = (lid & 3) * 2;
    float* outb = out + (size_t)b * COUT * HWSZ;
    #pragma unroll
    for (int mi = 0; mi < 2; mi++) {
        int qa = q0 + mwarp * 32 + mi * 16 + gr;
        int qb = qa + 8;
        int ha = qa / PADW - 1, wa = qa % PADW - 1;
        int hb = qb / PADW - 1, wb = qb % PADW - 1;
        bool va = ((unsigned)ha < HH) && ((unsigned)wa < WW);
        bool vb = ((unsigned)hb < HH) && ((unsigned)wb < WW);
        int pa = ha * WW + wa, pb = hb * WW + wb;
        #pragma unroll
        for (int ni = 0; ni < 8; ni++) {
            int n = n0 + nwarp * 64 + ni * 8 + c2;
            float* p = outb + (size_t)n * HWSZ;
            if (va) { p[pa] = acc[mi][ni][0]; p[HWSZ + pa] = acc[mi][ni][1]; }
            if (vb) { p[pb] = acc[mi][ni][2]; p[HWSZ + pb] = acc[mi][ni][3]; }
        }
    }
}

// ---------------------------------------------------------------------------
extern "C" void kernel_launch(void* const* d_in, const int* in_sizes, int n_in,
                              void* d_out, int out_size) {
    const float* x      = (const float*)d_in[0];  // (32,256,56,56)
    const float* att_w  = (const float*)d_in[1];  // (4,256)
    const float* weight = (const float*)d_in[2];  // (4,256,256,3,3)
    float* out = (float*)d_out;                   // (32,256,56,56)

    cudaFuncSetAttribute(conv_mma, cudaFuncAttributeMaxDynamicSharedMemorySize,
                         SMEM_BYTES_MMA);

    mean_kernel<<<BATCH * CIN, 256>>>(x);
    transpose_kernel<<<dim3(98, 4, BATCH), 256>>>(x);
    att_kernel<<<1, 128>>>(att_w);
    wprep_kernel<<<COUT, 256>>>(weight);
    conv_mma<<<dim3(MTILES * 2, BATCH), 256, SMEM_BYTES_MMA>>>(out);
}

// round 17
// speedup vs baseline: 1.4636x; 1.0346x over previous
#include <cuda_runtime.h>
#include <cuda_fp16.h>
#include <math.h>
#include <stdint.h>

#define BATCH 32
#define CIN   256
#define COUT  256
#define NEXP  4
#define HH    56
#define WW    56
#define HWSZ  3136

#define PADW    58
#define QCNT    3364           // 58*58 padded positions
#define GUARD   64
#define ROWSPAD 3712           // GUARD + 28*128 + GUARD
#define MTILES  27             // ceil(3364/128)

// ---------------------------------------------------------------------------
// Scratch (__device__ globals zero-initialized; guard/border rows stay 0)
// ---------------------------------------------------------------------------
__device__ float g_pooled[BATCH * CIN];        // per-(b,c) spatial mean
__device__ float g_att[BATCH * NEXP];
__device__ float g_part[BATCH * 4 * 98 * 64];  // transpose partial sums
__device__ __half g_xt[(size_t)BATCH * ROWSPAD * CIN];
__device__ __half g_wf[(size_t)BATCH * 9 * COUT * CIN];

// ---------------------------------------------------------------------------
// PTX helpers (compute_80-era: valid on compute_103 base target)
// ---------------------------------------------------------------------------
__device__ __forceinline__ uint32_t smem_u32(const void* p) {
    uint32_t a;
    asm("{ .reg .u64 t; cvta.to.shared.u64 t, %1; cvt.u32.u64 %0, t; }"
        : "=r"(a) : "l"(p));
    return a;
}
#define CP_ASYNC16(dst, src) \
    asm volatile("cp.async.cg.shared.global [%0], [%1], 16;" \
                 :: "r"(dst), "l"(src) : "memory")
#define CP_COMMIT() asm volatile("cp.async.commit_group;" ::: "memory")
#define CP_WAIT1()  asm volatile("cp.async.wait_group 1;" ::: "memory")

#define LDSM4(r, addr) \
    asm volatile("ldmatrix.sync.aligned.m8n8.x4.shared.b16 {%0,%1,%2,%3}, [%4];" \
                 : "=r"((r)[0]), "=r"((r)[1]), "=r"((r)[2]), "=r"((r)[3]) \
                 : "r"(addr))

#define MMA16816(d, a, b0, b1) \
    asm volatile("mma.sync.aligned.m16n8k16.row.col.f32.f16.f16.f32 " \
                 "{%0,%1,%2,%3}, {%4,%5,%6,%7}, {%8,%9}, {%0,%1,%2,%3};" \
                 : "+f"((d)[0]), "+f"((d)[1]), "+f"((d)[2]), "+f"((d)[3]) \
                 : "r"((a)[0]), "r"((a)[1]), "r"((a)[2]), "r"((a)[3]), \
                   "r"(b0), "r"(b1))

// ---------------------------------------------------------------------------
// Kernel 1: transpose x -> padded position-major fp16, PLUS atomic-FREE
// partial spatial sums (each block owns a private g_part slot).
// ---------------------------------------------------------------------------
__global__ void __launch_bounds__(256) transpose_kernel(const float* __restrict__ x) {
    __shared__ float tile[64][33];
    int b   = blockIdx.z;
    int ci0 = blockIdx.y * 64;
    int p0  = blockIdx.x * 32;
    int tid = threadIdx.x;
    int px = tid & 31, cir = tid >> 5;
    #pragma unroll
    for (int i = 0; i < 8; i++) {
        int ci = cir * 8 + i;
        tile[ci][px] = x[((size_t)b * CIN + ci0 + ci) * HWSZ + p0 + px];
    }
    __syncthreads();
    // partial mean: threads 0..63 each sum their ci row over the 32 pixels
    // (bank-conflict-free: addr = tid*33 + j), private slot -> no atomics
    if (tid < 64) {
        float s = 0.f;
        #pragma unroll
        for (int j = 0; j < 32; j++) s += tile[tid][j];
        g_part[(((size_t)b * 4 + blockIdx.y) * 98 + blockIdx.x) * 64 + tid] = s;
    }
    int cc = tid & 7, r = tid >> 3;
    int p = p0 + r;
    int h = p / WW, w = p % WW;
    size_t row = (size_t)b * ROWSPAD + GUARD + (size_t)(h + 1) * PADW + (w + 1);
    __align__(16) __half h8[8];
    #pragma unroll
    for (int j = 0; j < 8; j++)
        h8[j] = __float2half_rn(tile[cc * 8 + j][r]);
    *reinterpret_cast<uint4*>(g_xt + row * CIN + ci0 + cc * 8) =
        *reinterpret_cast<const uint4*>(h8);
}

// ---------------------------------------------------------------------------
// Kernel 2: reduce the 98 partials per (b,ci) -> g_pooled (L2-resident data)
// ---------------------------------------------------------------------------
__global__ void __launch_bounds__(256) mean_reduce() {
    int b = blockIdx.x, ci = threadIdx.x;
    int cig = ci >> 6, cl = ci & 63;
    const float* p = g_part + (((size_t)b * 4 + cig) * 98) * 64 + cl;
    float s = 0.f;
    #pragma unroll 7
    for (int i = 0; i < 98; i++) s += p[(size_t)i * 64];
    g_pooled[b * CIN + ci] = s * (1.0f / (float)HWSZ);
}

// ---------------------------------------------------------------------------
// Kernel 3: att = sigmoid(pooled @ att_w^T). 1 block, 128 threads.
// ---------------------------------------------------------------------------
__global__ void att_kernel(const float* __restrict__ att_w) {
    int idx = threadIdx.x;
    int b = idx >> 2, k = idx & 3;
    const float* pr = g_pooled + b * CIN;
    const float* wr = att_w + k * CIN;
    float s = 0.f;
    #pragma unroll 8
    for (int c = 0; c < CIN; c++) s += pr[c] * wr[c];
    g_att[idx] = 1.0f / (1.0f + expf(-s));
}

// ---------------------------------------------------------------------------
// Kernel 4: lean wprep (measured 17us): reads g_att, one block per cout,
// stage 4-expert slice (36KB) once, sweep 32 batches, coalesced fp16 stores.
// ---------------------------------------------------------------------------
__global__ void __launch_bounds__(256) wprep_kernel(const float* __restrict__ weight) {
    __shared__ float ws[NEXP][CIN * 9];
    __shared__ float att_s[BATCH * NEXP];
    const int o = blockIdx.x, ci = threadIdx.x;
    if (threadIdx.x < BATCH * NEXP) att_s[threadIdx.x] = g_att[threadIdx.x];
    #pragma unroll
    for (int k = 0; k < NEXP; k++)
        for (int i = threadIdx.x; i < CIN * 9; i += 256)
            ws[k][i] = weight[((size_t)k * COUT + o) * (CIN * 9) + i];
    __syncthreads();
    for (int b = 0; b < BATCH; b++) {
        float a0 = att_s[b * NEXP + 0], a1 = att_s[b * NEXP + 1];
        float a2 = att_s[b * NEXP + 2], a3 = att_s[b * NEXP + 3];
        #pragma unroll
        for (int t = 0; t < 9; t++) {
            float v = a0 * ws[0][ci * 9 + t] + a1 * ws[1][ci * 9 + t]
                    + a2 * ws[2][ci * 9 + t] + a3 * ws[3][ci * 9 + t];
            g_wf[(((size_t)b * 9 + t) * COUT + o) * CIN + ci] = __float2half_rn(v);
        }
    }
}

// ---------------------------------------------------------------------------
// Kernel 5: implicit-GEMM conv — UNCHANGED R14 version (348.9us, frozen).
// ---------------------------------------------------------------------------
#define A_BYTES   32768
#define B_STG     16384
#define SMEM_BYTES_MMA (2 * A_BYTES + 3 * B_STG)
#define SWZ_RC(r, c) ((uint32_t)((r) * 128 + (((c) ^ ((r) & 7)) << 4)))

__global__ void __launch_bounds__(256, 2) conv_mma(float* __restrict__ out) {
    extern __shared__ char smem[];
    const uint32_t sbase = smem_u32(smem);
    const int tid = threadIdx.x, wid = tid >> 5, lid = tid & 31;
    const int b  = blockIdx.y;
    const int mt = blockIdx.x >> 1, nt = blockIdx.x & 1;
    const int q0 = mt * 128, n0 = nt * 128;
    const int mwarp = wid >> 1, nwarp = wid & 1;

    const __half* xsrc = g_xt + (size_t)b * ROWSPAD * CIN;
    const __half* wsrc = g_wf + (size_t)b * 9 * COUT * CIN;

    float acc[2][8][4];
    #pragma unroll
    for (int mi = 0; mi < 2; mi++)
        #pragma unroll
        for (int ni = 0; ni < 8; ni++)
            #pragma unroll
            for (int e = 0; e < 4; e++) acc[mi][ni][e] = 0.f;

    auto issueA = [&](int c4) {
        const int ci0 = c4 << 6;
        const uint32_t abuf = sbase + (uint32_t)(c4 & 1) * A_BYTES;
        #pragma unroll
        for (int i = 0; i < 8; i++) {
            int j = tid + i * 256;
            int r = j >> 3, c = j & 7;
            const __half* src = xsrc + (size_t)(q0 + r) * CIN + ci0 + c * 8;
            CP_ASYNC16(abuf + SWZ_RC(r, c), src);
        }
    };
    auto issueB = [&](int s) {
        const int c4 = s / 9, t = s - c4 * 9;
        const int ci0 = c4 << 6;
        const uint32_t stg = sbase + 2 * A_BYTES + (uint32_t)(s % 3) * B_STG;
        #pragma unroll
        for (int i = 0; i < 4; i++) {
            int j = tid + i * 256;
            int r = j >> 3, c = j & 7;
            const __half* src =
                wsrc + ((size_t)t * COUT + n0 + r) * CIN + ci0 + c * 8;
            CP_ASYNC16(stg + SWZ_RC(r, c), src);
        }
    };

    // Prologue: G0 = {A(0), B(0)}, G1 = {B(1)}
    issueA(0); issueB(0); CP_COMMIT();
    issueB(1); CP_COMMIT();

    const int lr = lid & 15, lc = lid >> 4;

    for (int s = 0; s < 36; s++) {
        const int c4 = s / 9, t = s - c4 * 9;
        CP_WAIT1();
        __syncthreads();
        if (t == 6 && c4 < 3) issueA(c4 + 1);
        if (s + 2 < 36) issueB(s + 2);
        CP_COMMIT();

        const int off = (t / 3 - 1) * PADW + (t % 3 - 1);
        const int arow0 = 64 + off + mwarp * 32;
        const uint32_t Abuf = sbase + (uint32_t)(c4 & 1) * A_BYTES;
        const uint32_t Bbuf = sbase + 2 * A_BYTES + (uint32_t)(s % 3) * B_STG;

        uint32_t af[2][2][4], bf[2][4][4];
        #pragma unroll
        for (int mi = 0; mi < 2; mi++) {
            int row = arow0 + mi * 16 + lr;
            LDSM4(af[0][mi], Abuf + row * 128 +
                  ((uint32_t)(lc ^ (row & 7)) << 4));
        }
        #pragma unroll
        for (int nj = 0; nj < 4; nj++) {
            int row = nwarp * 64 + nj * 16 + lr;
            LDSM4(bf[0][nj], Bbuf + row * 128 +
                  ((uint32_t)(lc ^ (row & 7)) << 4));
        }
        #pragma unroll
        for (int k16 = 0; k16 < 4; k16++) {
            const int cur = k16 & 1, nxt = cur ^ 1;
            if (k16 < 3) {
                #pragma unroll
                for (int mi = 0; mi < 2; mi++) {
                    int row = arow0 + mi * 16 + lr;
                    LDSM4(af[nxt][mi], Abuf + row * 128 +
                          ((uint32_t)(((k16 + 1) * 2 + lc) ^ (row & 7)) << 4));
                }
                #pragma unroll
                for (int nj = 0; nj < 4; nj++) {
                    int row = nwarp * 64 + nj * 16 + lr;
                    LDSM4(bf[nxt][nj], Bbuf + row * 128 +
                          ((uint32_t)(((k16 + 1) * 2 + lc) ^ (row & 7)) << 4));
                }
            }
            #pragma unroll
            for (int mi = 0; mi < 2; mi++)
                #pragma unroll
                for (int nj = 0; nj < 4; nj++) {
                    MMA16816(acc[mi][2 * nj + 0], af[cur][mi],
                             bf[cur][nj][0], bf[cur][nj][2]);
                    MMA16816(acc[mi][2 * nj + 1], af[cur][mi],
                             bf[cur][nj][1], bf[cur][nj][3]);
                }
        }
    }

    // ---- epilogue: scatter acc to out[b][cout][h*56+w] ----
    const int gr = lid >> 2, c2 = (lid & 3) * 2;
    float* outb = out + (size_t)b * COUT * HWSZ;
    #pragma unroll
    for (int mi = 0; mi < 2; mi++) {
        int qa = q0 + mwarp * 32 + mi * 16 + gr;
        int qb = qa + 8;
        int ha = qa / PADW - 1, wa = qa % PADW - 1;
        int hb = qb / PADW - 1, wb = qb % PADW - 1;
        bool va = ((unsigned)ha < HH) && ((unsigned)wa < WW);
        bool vb = ((unsigned)hb < HH) && ((unsigned)wb < WW);
        int pa = ha * WW + wa, pb = hb * WW + wb;
        #pragma unroll
        for (int ni = 0; ni < 8; ni++) {
            int n = n0 + nwarp * 64 + ni * 8 + c2;
            float* p = outb + (size_t)n * HWSZ;
            if (va) { p[pa] = acc[mi][ni][0]; p[HWSZ + pa] = acc[mi][ni][1]; }
            if (vb) { p[pb] = acc[mi][ni][2]; p[HWSZ + pb] = acc[mi][ni][3]; }
        }
    }
}

// ---------------------------------------------------------------------------
extern "C" void kernel_launch(void* const* d_in, const int* in_sizes, int n_in,
                              void* d_out, int out_size) {
    const float* x      = (const float*)d_in[0];  // (32,256,56,56)
    const float* att_w  = (const float*)d_in[1];  // (4,256)
    const float* weight = (const float*)d_in[2];  // (4,256,256,3,3)
    float* out = (float*)d_out;                   // (32,256,56,56)

    cudaFuncSetAttribute(conv_mma, cudaFuncAttributeMaxDynamicSharedMemorySize,
                         SMEM_BYTES_MMA);

    transpose_kernel<<<dim3(98, 4, BATCH), 256>>>(x);   // + partial sums
    mean_reduce<<<BATCH, 256>>>();
    att_kernel<<<1, 128>>>(att_w);
    wprep_kernel<<<COUT, 256>>>(weight);
    conv_mma<<<dim3(MTILES * 2, BATCH), 256, SMEM_BYTES_MMA>>>(out);
}